// round 10
// baseline (speedup 1.0000x reference)
#include <cuda_runtime.h>
#include <cuda_fp16.h>
#include <cuda_bf16.h>
#include <cstdint>
#include <cstddef>

#define HID 128
#define NMAX 100000
#define MMAX 800000
#define CMAX 1024
#define NCMAX 1000
#define CH 512
#define XSTR 68    // smem stride (floats) for k_input transposed tiles
#define ASTR 264   // smem stride (halfs) A planes
#define BSTR 136   // smem stride (halfs) B planes

typedef unsigned long long u64;

__device__ int    g_deg[NMAX];
__device__ int    g_rowstart[NMAX + 1];
__device__ int    g_pos[NMAX];
__device__ float  g_invdeg[NMAX];
__device__ int    g_csr[MMAX];
__device__ int    g_bsum[128];
__device__ int    g_boff[128];
__device__ float  g_h[(size_t)NMAX * HID];
__device__ __nv_bfloat16 g_hh[(size_t)NMAX * HID];
__device__ __nv_bfloat16 g_hl[(size_t)NMAX * HID];
__device__ __nv_bfloat16 g_aggh[(size_t)NMAX * HID];
__device__ __nv_bfloat16 g_aggl[(size_t)NMAX * HID];
__device__ __nv_bfloat16 g_wh[4 * 256 * HID];
__device__ __nv_bfloat16 g_wl[4 * 256 * HID];
__device__ float  g_base[NCMAX * HID];
__device__ float  g_partial[512 * HID];
__device__ float  g_ge[HID];
__device__ float  g_ce[CMAX * HID];
__device__ __half g_slab[(size_t)CMAX * NCMAX * HID];

__device__ __forceinline__ float gelu_f(float x) {
    return 0.5f * x * (1.0f + erff(x * 0.70710678f));
}
__device__ __forceinline__ float wred(float v) {
    #pragma unroll
    for (int o = 16; o; o >>= 1) v += __shfl_xor_sync(0xffffffffu, v, o);
    return v;
}
__device__ __forceinline__ u64 dup2(float a) {
    u64 r; asm("mov.b64 %0, {%1, %1};" : "=l"(r) : "f"(a)); return r;
}
__device__ __forceinline__ u64 pk2(float a, float b) {
    u64 r; asm("mov.b64 %0, {%1, %2};" : "=l"(r) : "f"(a), "f"(b)); return r;
}
__device__ __forceinline__ void fma2(u64& d, u64 a, u64 b) {
    asm("fma.rn.f32x2 %0, %1, %2, %0;" : "+l"(d) : "l"(a), "l"(b));
}
__device__ __forceinline__ float2 unpk(u64 v) {
    float2 r; asm("mov.b64 {%0, %1}, %2;" : "=f"(r.x), "=f"(r.y) : "l"(v)); return r;
}
__device__ __forceinline__ uint32_t s2u(const void* p) {
    uint32_t a;
    asm("{ .reg .u64 t; cvta.to.shared.u64 t, %1; cvt.u32.u64 %0, t; }" : "=r"(a) : "l"(p));
    return a;
}

// ---------------- graph prep ----------------
__global__ void k_zero(int N) {
    int i = blockIdx.x * blockDim.x + threadIdx.x;
    if (i < N) g_deg[i] = 0;
}
__global__ void k_deg(const int* __restrict__ ei, int M) {
    int e = blockIdx.x * blockDim.x + threadIdx.x;
    if (e < M) atomicAdd(&g_deg[ei[M + e]], 1);
}
__global__ void k_scan1(int N) {
    __shared__ int s[1024];
    int t = threadIdx.x, i = blockIdx.x * 1024 + t;
    s[t] = (i < N) ? g_deg[i] : 0;
    __syncthreads();
    for (int o = 1; o < 1024; o <<= 1) {
        int a = (t >= o) ? s[t - o] : 0;
        __syncthreads();
        s[t] += a;
        __syncthreads();
    }
    if (i < N) g_rowstart[i + 1] = s[t];
    if (t == 1023) g_bsum[blockIdx.x] = s[1023];
}
__global__ void k_scan2(int nb) {
    if (threadIdx.x == 0) {
        int run = 0;
        for (int b = 0; b < nb; ++b) { g_boff[b] = run; run += g_bsum[b]; }
    }
}
__global__ void k_scan3(int N) {
    int i = blockIdx.x * blockDim.x + threadIdx.x;
    if (i == 0) g_rowstart[0] = 0;
    if (i < N) g_rowstart[i + 1] += g_boff[i >> 10];
}
__global__ void k_posinv(int N) {
    int i = blockIdx.x * blockDim.x + threadIdx.x;
    if (i < N) {
        g_pos[i] = g_rowstart[i];
        int d = g_deg[i];
        g_invdeg[i] = 1.0f / (float)(d > 0 ? d : 1);
    }
}
__global__ void k_scatter(const int* __restrict__ ei, int M) {
    int e = blockIdx.x * blockDim.x + threadIdx.x;
    if (e < M) {
        int dst = ei[M + e];
        int slot = atomicAdd(&g_pos[dst], 1);
        g_csr[slot] = ei[e];
    }
}

// ---------------- weight split: fp32 -> bf16 hi/lo planes, [layer][256][128] ----------------
__global__ void k_wsplit(const float* __restrict__ Wl, const float* __restrict__ Wr) {
    int idx = blockIdx.x * blockDim.x + threadIdx.x;
    if (idx >= 4 * 256 * HID) return;
    int layer = idx >> 15;
    int r = (idx >> 7) & 255;
    int col = idx & 127;
    float x = (r < 128) ? Wl[(size_t)layer * 128 * HID + r * HID + col]
                        : Wr[(size_t)layer * 128 * HID + (r - 128) * HID + col];
    __nv_bfloat16 h = __float2bfloat16_rn(x);
    g_wh[idx] = h;
    g_wl[idx] = __float2bfloat16_rn(x - __bfloat162float(h));
}

// ---------------- input embed: f32x2 tiled GEMM + LN + GELU (+ bf16 split planes) ----------------
__global__ void k_input(const float* __restrict__ feat, const int* __restrict__ opcode,
                        const float* __restrict__ depth, const float* __restrict__ emb,
                        const float* __restrict__ W, const float* __restrict__ b,
                        const float* __restrict__ lg, const float* __restrict__ lb, int N) {
    extern __shared__ float xs[];   // [205][XSTR]
    int tid = threadIdx.x, lane = tid & 31, wp = tid >> 5;
    int n0 = blockIdx.x * 64;
    for (int i = tid; i < 64 * 140; i += 256) {
        int n = i / 140, k = i - n * 140;
        int gn = n0 + n; if (gn >= N) gn = N - 1;
        xs[k * XSTR + n] = feat[(size_t)gn * 140 + k];
    }
    for (int i = tid; i < 64 * 64; i += 256) {
        int n = i >> 6, k = i & 63;
        int gn = n0 + n; if (gn >= N) gn = N - 1;
        int op = opcode[gn]; op = op < 0 ? 0 : (op > 119 ? 119 : op);
        xs[(140 + k) * XSTR + n] = emb[op * 64 + k];
    }
    if (tid < 64) {
        int gn = n0 + tid; if (gn >= N) gn = N - 1;
        xs[204 * XSTR + tid] = depth[gn];
    }
    __syncthreads();

    int ng = wp, c0 = lane * 4;
    u64 acc2[4][4];
    #pragma unroll
    for (int p = 0; p < 4; ++p)
        #pragma unroll
        for (int c = 0; c < 4; ++c) acc2[p][c] = 0ull;
    #pragma unroll 2
    for (int k = 0; k < 205; ++k) {
        float4 w4 = *(const float4*)&W[k * HID + c0];
        u64 wd[4] = {dup2(w4.x), dup2(w4.y), dup2(w4.z), dup2(w4.w)};
        const u64* xp = (const u64*)&xs[k * XSTR + ng * 8];
        u64 xv[4] = {xp[0], xp[1], xp[2], xp[3]};
        #pragma unroll
        for (int p = 0; p < 4; ++p)
            #pragma unroll
            for (int c = 0; c < 4; ++c) fma2(acc2[p][c], xv[p], wd[c]);
    }
    float av[8][4];
    #pragma unroll
    for (int p = 0; p < 4; ++p)
        #pragma unroll
        for (int c = 0; c < 4; ++c) {
            float2 t = unpk(acc2[p][c]);
            av[2 * p][c] = t.x; av[2 * p + 1][c] = t.y;
        }
    float4 b4 = *(const float4*)&b[c0];
    float4 g4 = *(const float4*)&lg[c0];
    float4 e4 = *(const float4*)&lb[c0];
    float mu[8], iv[8];
    #pragma unroll
    for (int j = 0; j < 8; ++j) {
        av[j][0] += b4.x; av[j][1] += b4.y; av[j][2] += b4.z; av[j][3] += b4.w;
        mu[j] = wred(av[j][0] + av[j][1] + av[j][2] + av[j][3]) * (1.f / HID);
    }
    #pragma unroll
    for (int j = 0; j < 8; ++j) {
        float dx = av[j][0] - mu[j], dy = av[j][1] - mu[j];
        float dz = av[j][2] - mu[j], dw = av[j][3] - mu[j];
        iv[j] = rsqrtf(wred(dx * dx + dy * dy + dz * dz + dw * dw) * (1.f / HID) + 1e-5f);
    }
    #pragma unroll
    for (int j = 0; j < 8; ++j) {
        int gn = n0 + ng * 8 + j;
        if (gn < N) {
            float o0 = gelu_f((av[j][0] - mu[j]) * iv[j] * g4.x + e4.x);
            float o1 = gelu_f((av[j][1] - mu[j]) * iv[j] * g4.y + e4.y);
            float o2 = gelu_f((av[j][2] - mu[j]) * iv[j] * g4.z + e4.z);
            float o3 = gelu_f((av[j][3] - mu[j]) * iv[j] * g4.w + e4.w);
            *(float4*)&g_h[(size_t)gn * HID + c0] = make_float4(o0, o1, o2, o3);
            __nv_bfloat162 h0, h1, l0, l1;
            h0.x = __float2bfloat16_rn(o0); h0.y = __float2bfloat16_rn(o1);
            h1.x = __float2bfloat16_rn(o2); h1.y = __float2bfloat16_rn(o3);
            l0.x = __float2bfloat16_rn(o0 - __bfloat162float(h0.x));
            l0.y = __float2bfloat16_rn(o1 - __bfloat162float(h0.y));
            l1.x = __float2bfloat16_rn(o2 - __bfloat162float(h1.x));
            l1.y = __float2bfloat16_rn(o3 - __bfloat162float(h1.y));
            *(__nv_bfloat162*)&g_hh[(size_t)gn * HID + c0] = h0;
            *(__nv_bfloat162*)&g_hh[(size_t)gn * HID + c0 + 2] = h1;
            *(__nv_bfloat162*)&g_hl[(size_t)gn * HID + c0] = l0;
            *(__nv_bfloat162*)&g_hl[(size_t)gn * HID + c0 + 2] = l1;
        }
    }
}

// ---------------- mean aggregation: warp per node, writes bf16 hi/lo planes ----------------
__global__ void k_agg(int N) {
    int gw = (blockIdx.x * blockDim.x + threadIdx.x) >> 5;
    int lane = threadIdx.x & 31;
    if (gw >= N) return;
    int rs = g_rowstart[gw], re = g_rowstart[gw + 1];
    float4 acc = make_float4(0.f, 0.f, 0.f, 0.f);
    for (int e = rs; e < re; ++e) {
        int s = g_csr[e];
        float4 v = *(const float4*)&g_h[(size_t)s * HID + lane * 4];
        acc.x += v.x; acc.y += v.y; acc.z += v.z; acc.w += v.w;
    }
    float idg = g_invdeg[gw];
    acc.x *= idg; acc.y *= idg; acc.z *= idg; acc.w *= idg;
    __nv_bfloat162 h0, h1, l0, l1;
    h0.x = __float2bfloat16_rn(acc.x); h0.y = __float2bfloat16_rn(acc.y);
    h1.x = __float2bfloat16_rn(acc.z); h1.y = __float2bfloat16_rn(acc.w);
    l0.x = __float2bfloat16_rn(acc.x - __bfloat162float(h0.x));
    l0.y = __float2bfloat16_rn(acc.y - __bfloat162float(h0.y));
    l1.x = __float2bfloat16_rn(acc.z - __bfloat162float(h1.x));
    l1.y = __float2bfloat16_rn(acc.w - __bfloat162float(h1.y));
    size_t off = (size_t)gw * HID + lane * 4;
    *(__nv_bfloat162*)&g_aggh[off] = h0;
    *(__nv_bfloat162*)&g_aggh[off + 2] = h1;
    *(__nv_bfloat162*)&g_aggl[off] = l0;
    *(__nv_bfloat162*)&g_aggl[off + 2] = l1;
}

// ---------------- SAGE layer: bf16 3-mma split, 64 nodes x 128 cols, K=256 ----------------
__global__ void k_layer(const float* __restrict__ bl, const float* __restrict__ lg,
                        const float* __restrict__ lb, int layer, int N) {
    extern __shared__ char smb[];
    __nv_bfloat16* sAh = (__nv_bfloat16*)smb;                 // 33792 B
    __nv_bfloat16* sAl = (__nv_bfloat16*)(smb + 33792);       // 33792 B
    __nv_bfloat16* sBh = (__nv_bfloat16*)(smb + 67584);       // 69632 B
    __nv_bfloat16* sBl = (__nv_bfloat16*)(smb + 137216);      // 69632 B
    float* pS = (float*)(smb + 206848);                       // 256 f
    float* pQ = (float*)(smb + 207872);                       // 256 f
    int tid = threadIdx.x, lane = tid & 31, w = tid >> 5;
    int n0 = blockIdx.x * 64;

    #pragma unroll
    for (int it = 0; it < 16; ++it) {
        int c = it * 256 + tid;
        int plane = c >> 11, rc = c & 2047;
        int row = rc >> 5, chk = rc & 31;
        int gn = n0 + row; if (gn >= N) gn = N - 1;
        const __nv_bfloat16* src;
        if (chk < 16) src = (plane ? g_aggl : g_aggh) + (size_t)gn * HID + chk * 8;
        else          src = (plane ? g_hl : g_hh) + (size_t)gn * HID + (chk - 16) * 8;
        uint4 v = *(const uint4*)src;
        __nv_bfloat16* dst = (plane ? sAl : sAh) + row * ASTR + chk * 8;
        *(uint4*)dst = v;
    }
    {
        const __nv_bfloat16* wh = g_wh + layer * 256 * HID;
        const __nv_bfloat16* wl = g_wl + layer * 256 * HID;
        #pragma unroll
        for (int it = 0; it < 32; ++it) {
            int c = it * 256 + tid;
            int plane = c >> 12, rc = c & 4095;
            int row = rc >> 4, off = rc & 15;
            uint4 v = *(const uint4*)((plane ? wl : wh) + rc * 8);
            __nv_bfloat16* dst = (plane ? sBl : sBh) + row * BSTR + off * 8;
            *(uint4*)dst = v;
        }
    }
    __syncthreads();

    int mt = w >> 1, nh = w & 1;
    float d[8][4];
    #pragma unroll
    for (int j = 0; j < 8; ++j)
        #pragma unroll
        for (int e = 0; e < 4; ++e) d[j][e] = 0.f;

    int arow = mt * 16 + (lane & 7) + ((lane >> 3) & 1) * 8;
    uint32_t aAh = s2u(sAh) + (arow * ASTR + (lane >> 4) * 8) * 2;
    uint32_t aAl = aAh + 33792;
    int bk = lane & 15;
    uint32_t aB0 = s2u(sBh) + (bk * BSTR + nh * 64) * 2;

    for (int kt = 0; kt < 16; ++kt) {
        uint32_t ah0, ah1, ah2, ah3, al0, al1, al2, al3;
        asm volatile("ldmatrix.sync.aligned.m8n8.x4.shared.b16 {%0,%1,%2,%3}, [%4];"
                     : "=r"(ah0), "=r"(ah1), "=r"(ah2), "=r"(ah3) : "r"(aAh + kt * 32));
        asm volatile("ldmatrix.sync.aligned.m8n8.x4.shared.b16 {%0,%1,%2,%3}, [%4];"
                     : "=r"(al0), "=r"(al1), "=r"(al2), "=r"(al3) : "r"(aAl + kt * 32));
        uint32_t bbase = aB0 + kt * 16 * BSTR * 2;
        #pragma unroll
        for (int j = 0; j < 8; ++j) {
            uint32_t bh0, bh1, bl0, bl1;
            asm volatile("ldmatrix.sync.aligned.m8n8.x2.trans.shared.b16 {%0,%1}, [%2];"
                         : "=r"(bh0), "=r"(bh1) : "r"(bbase + j * 16));
            asm volatile("ldmatrix.sync.aligned.m8n8.x2.trans.shared.b16 {%0,%1}, [%2];"
                         : "=r"(bl0), "=r"(bl1) : "r"(bbase + j * 16 + 69632));
            asm volatile("mma.sync.aligned.m16n8k16.row.col.f32.bf16.bf16.f32 "
                         "{%0,%1,%2,%3}, {%4,%5,%6,%7}, {%8,%9}, {%0,%1,%2,%3};"
                         : "+f"(d[j][0]), "+f"(d[j][1]), "+f"(d[j][2]), "+f"(d[j][3])
                         : "r"(ah0), "r"(ah1), "r"(ah2), "r"(ah3), "r"(bh0), "r"(bh1));
            asm volatile("mma.sync.aligned.m16n8k16.row.col.f32.bf16.bf16.f32 "
                         "{%0,%1,%2,%3}, {%4,%5,%6,%7}, {%8,%9}, {%0,%1,%2,%3};"
                         : "+f"(d[j][0]), "+f"(d[j][1]), "+f"(d[j][2]), "+f"(d[j][3])
                         : "r"(al0), "r"(al1), "r"(al2), "r"(al3), "r"(bh0), "r"(bh1));
            asm volatile("mma.sync.aligned.m16n8k16.row.col.f32.bf16.bf16.f32 "
                         "{%0,%1,%2,%3}, {%4,%5,%6,%7}, {%8,%9}, {%0,%1,%2,%3};"
                         : "+f"(d[j][0]), "+f"(d[j][1]), "+f"(d[j][2]), "+f"(d[j][3])
                         : "r"(ah0), "r"(ah1), "r"(ah2), "r"(ah3), "r"(bl0), "r"(bl1));
        }
    }

    int g = lane >> 2, q = lane & 3;
    int lr0 = mt * 16 + g, lr1 = lr0 + 8;
    int gn0 = n0 + lr0, gn1 = n0 + lr1;
    int cg0 = gn0 < N ? gn0 : N - 1, cg1 = gn1 < N ? gn1 : N - 1;
    float s0 = 0.f, s1 = 0.f, q0 = 0.f, q1 = 0.f;
    #pragma unroll
    for (int j = 0; j < 8; ++j) {
        int cp = nh * 64 + j * 8 + 2 * q;
        float2 bb = *(const float2*)&bl[cp];
        float2 h0 = *(const float2*)&g_h[(size_t)cg0 * HID + cp];
        float2 h1 = *(const float2*)&g_h[(size_t)cg1 * HID + cp];
        float y00 = h0.x + gelu_f(d[j][0] + bb.x);
        float y01 = h0.y + gelu_f(d[j][1] + bb.y);
        float y10 = h1.x + gelu_f(d[j][2] + bb.x);
        float y11 = h1.y + gelu_f(d[j][3] + bb.y);
        d[j][0] = y00; d[j][1] = y01; d[j][2] = y10; d[j][3] = y11;
        s0 += y00 + y01; s1 += y10 + y11;
        q0 += y00 * y00 + y01 * y01; q1 += y10 * y10 + y11 * y11;
    }
    #pragma unroll
    for (int o = 1; o <= 2; o <<= 1) {
        s0 += __shfl_xor_sync(0xffffffffu, s0, o);
        s1 += __shfl_xor_sync(0xffffffffu, s1, o);
        q0 += __shfl_xor_sync(0xffffffffu, q0, o);
        q1 += __shfl_xor_sync(0xffffffffu, q1, o);
    }
    if (q == 0) {
        pS[lr0 * 2 + nh] = s0; pS[lr1 * 2 + nh] = s1;
        pQ[lr0 * 2 + nh] = q0; pQ[lr1 * 2 + nh] = q1;
    }
    __syncthreads();
    float mu0 = (pS[lr0 * 2] + pS[lr0 * 2 + 1]) * (1.f / HID);
    float mu1 = (pS[lr1 * 2] + pS[lr1 * 2 + 1]) * (1.f / HID);
    float v0 = (pQ[lr0 * 2] + pQ[lr0 * 2 + 1]) * (1.f / HID) - mu0 * mu0;
    float v1 = (pQ[lr1 * 2] + pQ[lr1 * 2 + 1]) * (1.f / HID) - mu1 * mu1;
    float iv0 = rsqrtf(v0 + 1e-5f), iv1 = rsqrtf(v1 + 1e-5f);
    #pragma unroll
    for (int j = 0; j < 8; ++j) {
        int cp = nh * 64 + j * 8 + 2 * q;
        float2 lgp = *(const float2*)&lg[cp];
        float2 lbp = *(const float2*)&lb[cp];
        if (gn0 < N) {
            float ox = (d[j][0] - mu0) * iv0 * lgp.x + lbp.x;
            float oy = (d[j][1] - mu0) * iv0 * lgp.y + lbp.y;
            *(float2*)&g_h[(size_t)gn0 * HID + cp] = make_float2(ox, oy);
            __nv_bfloat162 hh, ll;
            hh.x = __float2bfloat16_rn(ox); hh.y = __float2bfloat16_rn(oy);
            ll.x = __float2bfloat16_rn(ox - __bfloat162float(hh.x));
            ll.y = __float2bfloat16_rn(oy - __bfloat162float(hh.y));
            *(__nv_bfloat162*)&g_hh[(size_t)gn0 * HID + cp] = hh;
            *(__nv_bfloat162*)&g_hl[(size_t)gn0 * HID + cp] = ll;
        }
        if (gn1 < N) {
            float ox = (d[j][2] - mu1) * iv1 * lgp.x + lbp.x;
            float oy = (d[j][3] - mu1) * iv1 * lgp.y + lbp.y;
            *(float2*)&g_h[(size_t)gn1 * HID + cp] = make_float2(ox, oy);
            __nv_bfloat162 hh, ll;
            hh.x = __float2bfloat16_rn(ox); hh.y = __float2bfloat16_rn(oy);
            ll.x = __float2bfloat16_rn(ox - __bfloat162float(hh.x));
            ll.y = __float2bfloat16_rn(oy - __bfloat162float(hh.y));
            *(__nv_bfloat162*)&g_hh[(size_t)gn1 * HID + cp] = hh;
            *(__nv_bfloat162*)&g_hl[(size_t)gn1 * HID + cp] = ll;
        }
    }
}

// ---------------- global mean of h (deterministic 2-stage) ----------------
__global__ void k_gmean1(int N) {
    int col = threadIdx.x, blk = blockIdx.x;
    int per = (N + 511) / 512;
    int a = blk * per, b = a + per; if (b > N) b = N;
    float acc = 0.f;
    for (int n = a; n < b; ++n) acc += g_h[(size_t)n * HID + col];
    g_partial[blk * HID + col] = acc;
}
__global__ void k_gmean2(int N) {
    int col = threadIdx.x;
    float acc = 0.f;
    for (int b = 0; b < 512; ++b) acc += g_partial[b * HID + col];
    g_ge[col] = acc / (float)N;
}

// ---------------- base[nc] = h[cfg_id[nc]] @ cfg_w[:128] + cfg_b ----------------
__global__ void k_base(const int* __restrict__ ids, const float* __restrict__ W,
                       const float* __restrict__ b, int NC) {
    __shared__ float row[HID];
    int nc = blockIdx.x, col = threadIdx.x;
    int nd = ids[nc];
    row[col] = g_h[(size_t)nd * HID + col];
    __syncthreads();
    float acc = b[col];
    for (int k = 0; k < HID; ++k) acc += row[k] * W[k * HID + col];
    g_base[nc * HID + col] = acc;
}

// ---------------- scoring: 256 workers x 2 packed configs; halved LDS traffic ----------------
__global__ void __launch_bounds__(512) k_score(
        const float* __restrict__ cfgf, const float* __restrict__ cfg_w,
        const float* __restrict__ w1, const float* __restrict__ b1,
        const float* __restrict__ w2s, const float* __restrict__ b2,
        const float* __restrict__ temp, int C, int NC) {
    extern __shared__ unsigned char smx[];
    __half* projs = (__half*)smx;                      // 512*128
    float* base_s = (float*)(smx + CH * HID * 2);      // 128
    float* w18 = base_s + HID;                         // 18*128
    float* sw1 = w18 + 18 * HID;                       // 128*16
    float* sw2 = sw1 + HID * 16;                       // 16*128
    float* sb1 = sw2 + 16 * HID;                       // 16
    float* sb2 = sb1 + 16;                             // 128
    int tid = threadIdx.x;
    int chunk = blockIdx.x, nc = blockIdx.y;
    for (int i = tid; i < 18 * HID; i += CH) w18[i] = cfg_w[128 * HID + i];
    for (int i = tid; i < HID * 16; i += CH) sw1[i] = w1[i];
    for (int i = tid; i < 16 * HID; i += CH) sw2[i] = w2s[i];
    if (tid < 16) sb1[tid] = b1[tid];
    if (tid < HID) sb2[tid] = b2[tid];
    if (tid < HID) base_s[tid] = g_base[nc * HID + tid];
    __syncthreads();

    if (tid < 256) {
        int c0 = tid, c1 = tid + 256;
        int cg0 = chunk * CH + c0, cg1 = chunk * CH + c1;
        const float* f0p = &cfgf[((size_t)cg0 * NC + nc) * 18];
        const float* f1p = &cfgf[((size_t)cg1 * NC + nc) * 18];
        u64 fd[18];
        #pragma unroll
        for (int j = 0; j < 18; ++j) fd[j] = pk2(f0p[j], f1p[j]);
        u64 s1p[16];
        #pragma unroll
        for (int r = 0; r < 16; ++r) s1p[r] = dup2(sb1[r]);
        for (int col = 0; col < HID; col += 2) {
            float2 bsp = *(const float2*)&base_s[col];
            u64 v0 = dup2(bsp.x), v1 = dup2(bsp.y);   // packed (c0,c1) for col, col+1
            #pragma unroll
            for (int j = 0; j < 18; ++j) {
                float2 wv = *(const float2*)&w18[j * HID + col];
                fma2(v0, fd[j], dup2(wv.x));
                fma2(v1, fd[j], dup2(wv.y));
            }
            float2 va = unpk(v0), vb = unpk(v1);
            float p00 = gelu_f(va.x), p01 = gelu_f(va.y);
            float p10 = gelu_f(vb.x), p11 = gelu_f(vb.y);
            projs[col * CH + c0] = __float2half(p00);
            projs[col * CH + c1] = __float2half(p01);
            projs[(col + 1) * CH + c0] = __float2half(p10);
            projs[(col + 1) * CH + c1] = __float2half(p11);
            u64 vp0 = pk2(p00, p01), vp1 = pk2(p10, p11);
            #pragma unroll
            for (int r = 0; r < 16; ++r) {
                fma2(s1p[r], vp0, dup2(sw1[col * 16 + r]));
                fma2(s1p[r], vp1, dup2(sw1[(col + 1) * 16 + r]));
            }
        }
        #pragma unroll
        for (int r = 0; r < 16; ++r) {
            float2 t = unpk(s1p[r]);
            s1p[r] = pk2(fmaxf(t.x, 0.f), fmaxf(t.y, 0.f));
        }
        for (int col = 0; col < HID; col += 2) {
            float2 bp = *(const float2*)&sb2[col];
            u64 z0 = dup2(bp.x), z1 = dup2(bp.y);
            #pragma unroll
            for (int r = 0; r < 16; ++r) {
                float2 wz = *(const float2*)&sw2[r * HID + col];
                fma2(z0, s1p[r], dup2(wz.x));
                fma2(z1, s1p[r], dup2(wz.y));
            }
            float2 za = unpk(z0), zb = unpk(z1);
            float sc00 = 1.f / (1.f + __expf(-za.x));
            float sc01 = 1.f / (1.f + __expf(-za.y));
            float sc10 = 1.f / (1.f + __expf(-zb.x));
            float sc11 = 1.f / (1.f + __expf(-zb.y));
            projs[col * CH + c0] = __float2half(__half2float(projs[col * CH + c0]) * sc00);
            projs[col * CH + c1] = __float2half(__half2float(projs[col * CH + c1]) * sc01);
            projs[(col + 1) * CH + c0] = __float2half(__half2float(projs[(col + 1) * CH + c0]) * sc10);
            projs[(col + 1) * CH + c1] = __float2half(__half2float(projs[(col + 1) * CH + c1]) * sc11);
        }
    }
    __syncthreads();

    float invT = 1.f / temp[0];
    int lane = tid & 31, wid = tid >> 5;
    for (int ci = 0; ci < 8; ++ci) {
        int col = wid + ci * 16;
        float v[16], m = -1e30f;
        #pragma unroll
        for (int i = 0; i < 16; ++i) {
            v[i] = __half2float(projs[col * CH + lane + i * 32]);
            m = fmaxf(m, v[i]);
        }
        #pragma unroll
        for (int o = 16; o; o >>= 1) m = fmaxf(m, __shfl_xor_sync(0xffffffffu, m, o));
        float ex[16];
        float se = 0.f;
        #pragma unroll
        for (int i = 0; i < 16; ++i) { ex[i] = __expf((v[i] - m) * invT); se += ex[i]; }
        se = wred(se);
        float inv_se = 1.f / se;
        #pragma unroll
        for (int i = 0; i < 16; ++i)
            projs[col * CH + lane + i * 32] = __float2half(v[i] * ex[i] * inv_se);
    }
    __syncthreads();
    for (int i = tid; i < CH * HID; i += CH) {
        int cl = i >> 7, col = i & 127;
        g_slab[((size_t)(chunk * CH + cl) * NC + nc) * HID + col] = projs[col * CH + cl];
    }
}

// ---------------- slab reduce ----------------
__global__ void k_reduce(int C, int NC) {
    __shared__ float red[8][HID];
    int c = blockIdx.x, tid = threadIdx.x;
    int cg = (tid & 15) * 8, rg = tid >> 4;
    float a[8];
    #pragma unroll
    for (int i = 0; i < 8; ++i) a[i] = 0.f;
    for (int nc = rg; nc < NC; nc += 8) {
        uint4 v = *(const uint4*)&g_slab[((size_t)c * NC + nc) * HID + cg];
        const __half2* h2 = (const __half2*)&v;
        #pragma unroll
        for (int i = 0; i < 4; ++i) {
            float2 f = __half22float2(h2[i]);
            a[2 * i] += f.x; a[2 * i + 1] += f.y;
        }
    }
    #pragma unroll
    for (int i = 0; i < 8; ++i) red[rg][cg + i] = a[i];
    __syncthreads();
    if (tid < HID) {
        float s = 0.f;
        #pragma unroll
        for (int r = 0; r < 8; ++r) s += red[r][tid];
        g_ce[c * HID + tid] = s / (float)NC;
    }
}

// ---------------- head MLP ----------------
__global__ void k_head(const float* __restrict__ w1, const float* __restrict__ b1,
                       const float* __restrict__ w2, const float* __restrict__ b2,
                       const float* __restrict__ w3, const float* __restrict__ b3,
                       float* __restrict__ out, int N, int C) {
    __shared__ float ges[HID], ces[HID], x1[HID], x2[64];
    int c = blockIdx.x, col = threadIdx.x;
    ges[col] = g_ge[col];
    ces[col] = g_ce[c * HID + col];
    __syncthreads();
    float acc = b1[col];
    for (int k = 0; k < HID; ++k) acc += ges[k] * w1[k * HID + col];
    for (int k = 0; k < HID; ++k) acc += ces[k] * w1[(HID + k) * HID + col];
    x1[col] = gelu_f(acc);
    __syncthreads();
    if (col < 64) {
        float a2 = b2[col];
        for (int k = 0; k < HID; ++k) a2 += x1[k] * w2[k * 64 + col];
        x2[col] = gelu_f(a2);
    }
    __syncthreads();
    if (col == 0) {
        float s = b3[0];
        for (int k = 0; k < 64; ++k) s += x2[k] * w3[k];
        out[c] = s;
    }
}

extern "C" void kernel_launch(void* const* d_in, const int* in_sizes, int n_in,
                              void* d_out, int out_size) {
    const float* node_feat = (const float*)d_in[0];
    const int*   node_opc  = (const int*)d_in[1];
    const float* topo      = (const float*)d_in[2];
    const int*   ei        = (const int*)d_in[3];
    const int*   cfg_ids   = (const int*)d_in[4];
    const float* cfg_feat  = (const float*)d_in[5];
    const float* temp      = (const float*)d_in[6];
    const float* opc_emb   = (const float*)d_in[7];
    const float* in_w      = (const float*)d_in[8];
    const float* in_b      = (const float*)d_in[9];
    const float* in_g      = (const float*)d_in[10];
    const float* in_beta   = (const float*)d_in[11];
    const float* sage_Wl   = (const float*)d_in[12];
    const float* sage_bl   = (const float*)d_in[13];
    const float* sage_Wr   = (const float*)d_in[14];
    const float* ln_g      = (const float*)d_in[15];
    const float* ln_b      = (const float*)d_in[16];
    const float* cfg_w     = (const float*)d_in[17];
    const float* cfg_b     = (const float*)d_in[18];
    const float* se_w1     = (const float*)d_in[19];
    const float* se_b1     = (const float*)d_in[20];
    const float* se_w2     = (const float*)d_in[21];
    const float* se_b2     = (const float*)d_in[22];
    const float* h_w1      = (const float*)d_in[23];
    const float* h_b1      = (const float*)d_in[24];
    const float* h_w2      = (const float*)d_in[25];
    const float* h_b2      = (const float*)d_in[26];
    const float* h_w3      = (const float*)d_in[27];
    const float* h_b3      = (const float*)d_in[28];

    int N  = in_sizes[1];
    int M  = in_sizes[3] / 2;
    int NC = in_sizes[4];
    int C  = in_sizes[5] / (NC * 18);
    int chunks = C / CH;
    int nblk = (N + 63) / 64;

    size_t in_smem = (size_t)205 * XSTR * 4;
    size_t ly_smem = 208896;
    cudaFuncSetAttribute(k_input, cudaFuncAttributeMaxDynamicSharedMemorySize, (int)in_smem);
    cudaFuncSetAttribute(k_layer, cudaFuncAttributeMaxDynamicSharedMemorySize, (int)ly_smem);

    k_zero<<<(N + 255) / 256, 256>>>(N);
    k_deg<<<(M + 255) / 256, 256>>>(ei, M);
    int sb = (N + 1023) / 1024;
    k_scan1<<<sb, 1024>>>(N);
    k_input<<<nblk, 256, in_smem>>>(node_feat, node_opc, topo, opc_emb,
                                    in_w, in_b, in_g, in_beta, N);
    k_wsplit<<<(4 * 256 * HID + 255) / 256, 256>>>(sage_Wl, sage_Wr);
    k_scan2<<<1, 32>>>(sb);
    k_scan3<<<(N + 255) / 256, 256>>>(N);
    k_posinv<<<(N + 255) / 256, 256>>>(N);
    k_scatter<<<(M + 255) / 256, 256>>>(ei, M);
    for (int l = 0; l < 4; ++l) {
        k_agg<<<(N + 7) / 8, 256>>>(N);
        k_layer<<<nblk, 256, ly_smem>>>(sage_bl + l * HID,
                                        ln_g + l * HID, ln_b + l * HID, l, N);
    }
    k_gmean1<<<512, 128>>>(N);
    k_gmean2<<<1, 128>>>(N);
    k_base<<<NC, 128>>>(cfg_ids, cfg_w, cfg_b, NC);

    size_t score_smem = (size_t)CH * HID * 2 +
                        (HID + 18 * HID + HID * 16 + 16 * HID + 16 + HID) * sizeof(float);
    cudaFuncSetAttribute(k_score, cudaFuncAttributeMaxDynamicSharedMemorySize, (int)score_smem);
    dim3 sg(chunks, NC);
    k_score<<<sg, CH, score_smem>>>(cfg_feat, cfg_w, se_w1, se_b1, se_w2, se_b2,
                                    temp, C, NC);
    k_reduce<<<C, 128>>>(C, NC);
    k_head<<<C, 128>>>(h_w1, h_b1, h_w2, h_b2, h_w3, h_b3, (float*)d_out, N, C);
}

// round 11
// speedup vs baseline: 1.1009x; 1.1009x over previous
#include <cuda_runtime.h>
#include <cuda_fp16.h>
#include <cuda_bf16.h>
#include <cstdint>
#include <cstddef>

#define HID 128
#define NMAX 100000
#define MMAX 800000
#define CMAX 1024
#define NCMAX 1000
#define CH 512
#define XSTR 68    // smem stride (floats) for k_input transposed tiles
#define ASTR 264   // smem stride (halfs) A planes

typedef unsigned long long u64;

__device__ int    g_deg[NMAX];
__device__ int    g_rowstart[NMAX + 1];
__device__ int    g_pos[NMAX];
__device__ float  g_invdeg[NMAX];
__device__ int    g_csr[MMAX];
__device__ int    g_bsum[128];
__device__ int    g_boff[128];
__device__ float  g_h[(size_t)NMAX * HID];
__device__ __nv_bfloat16 g_hh[(size_t)NMAX * HID];
__device__ __nv_bfloat16 g_hl[(size_t)NMAX * HID];
__device__ __nv_bfloat16 g_aggh[(size_t)NMAX * HID];
__device__ __nv_bfloat16 g_aggl[(size_t)NMAX * HID];
__device__ uint2  g_wfh[4 * 16 * 16 * 32];   // B fragments, hi plane
__device__ uint2  g_wfl[4 * 16 * 16 * 32];   // B fragments, lo plane
__device__ float  g_base[NCMAX * HID];
__device__ float  g_partial[512 * HID];
__device__ float  g_ge[HID];
__device__ float  g_ce[CMAX * HID];
__device__ __half g_slab[(size_t)CMAX * NCMAX * HID];

__device__ __forceinline__ float gelu_f(float x) {
    return 0.5f * x * (1.0f + erff(x * 0.70710678f));
}
__device__ __forceinline__ float wred(float v) {
    #pragma unroll
    for (int o = 16; o; o >>= 1) v += __shfl_xor_sync(0xffffffffu, v, o);
    return v;
}
__device__ __forceinline__ u64 dup2(float a) {
    u64 r; asm("mov.b64 %0, {%1, %1};" : "=l"(r) : "f"(a)); return r;
}
__device__ __forceinline__ void fma2(u64& d, u64 a, u64 b) {
    asm("fma.rn.f32x2 %0, %1, %2, %0;" : "+l"(d) : "l"(a), "l"(b));
}
__device__ __forceinline__ float2 unpk(u64 v) {
    float2 r; asm("mov.b64 {%0, %1}, %2;" : "=f"(r.x), "=f"(r.y) : "l"(v)); return r;
}
__device__ __forceinline__ uint32_t s2u(const void* p) {
    uint32_t a;
    asm("{ .reg .u64 t; cvta.to.shared.u64 t, %1; cvt.u32.u64 %0, t; }" : "=r"(a) : "l"(p));
    return a;
}

// ---------------- graph prep ----------------
__global__ void k_zero(int N) {
    int i = blockIdx.x * blockDim.x + threadIdx.x;
    if (i < N) g_deg[i] = 0;
}
__global__ void k_deg(const int* __restrict__ ei, int M) {
    int e = blockIdx.x * blockDim.x + threadIdx.x;
    if (e < M) atomicAdd(&g_deg[ei[M + e]], 1);
}
__global__ void k_scan1(int N) {
    __shared__ int s[1024];
    int t = threadIdx.x, i = blockIdx.x * 1024 + t;
    s[t] = (i < N) ? g_deg[i] : 0;
    __syncthreads();
    for (int o = 1; o < 1024; o <<= 1) {
        int a = (t >= o) ? s[t - o] : 0;
        __syncthreads();
        s[t] += a;
        __syncthreads();
    }
    if (i < N) g_rowstart[i + 1] = s[t];
    if (t == 1023) g_bsum[blockIdx.x] = s[1023];
}
__global__ void k_scan2(int nb) {
    if (threadIdx.x == 0) {
        int run = 0;
        for (int b = 0; b < nb; ++b) { g_boff[b] = run; run += g_bsum[b]; }
    }
}
__global__ void k_scan3(int N) {
    int i = blockIdx.x * blockDim.x + threadIdx.x;
    if (i == 0) g_rowstart[0] = 0;
    if (i < N) g_rowstart[i + 1] += g_boff[i >> 10];
}
__global__ void k_posinv(int N) {
    int i = blockIdx.x * blockDim.x + threadIdx.x;
    if (i < N) {
        g_pos[i] = g_rowstart[i];
        int d = g_deg[i];
        g_invdeg[i] = 1.0f / (float)(d > 0 ? d : 1);
    }
}
__global__ void k_scatter(const int* __restrict__ ei, int M) {
    int e = blockIdx.x * blockDim.x + threadIdx.x;
    if (e < M) {
        int dst = ei[M + e];
        int slot = atomicAdd(&g_pos[dst], 1);
        g_csr[slot] = ei[e];
    }
}

// ---------------- weight split into mma B-fragment layout ----------------
// B = [Wl;Wr] (256 x 128). Fragment (kt,nt,lane): reg0 = (B[k0][n], B[k0+1][n]),
// reg1 = (B[k0+8][n], B[k0+9][n]) with k0 = kt*16 + (lane&3)*2, n = nt*8 + (lane>>2).
__global__ void k_wsplit(const float* __restrict__ Wl, const float* __restrict__ Wr) {
    int idx = blockIdx.x * blockDim.x + threadIdx.x;
    if (idx >= 4 * 16 * 16 * 32) return;
    int lane = idx & 31;
    int nt = (idx >> 5) & 15;
    int kt = (idx >> 9) & 15;
    int layer = idx >> 13;
    int k0 = kt * 16 + (lane & 3) * 2;
    int n = nt * 8 + (lane >> 2);
    float v[4];
    #pragma unroll
    for (int e = 0; e < 4; ++e) {
        int k = k0 + (e & 1) + (e >> 1) * 8;
        v[e] = (k < 128) ? Wl[(size_t)layer * 128 * HID + k * HID + n]
                         : Wr[(size_t)layer * 128 * HID + (k - 128) * HID + n];
    }
    uint16_t hb[4], lb_[4];
    #pragma unroll
    for (int e = 0; e < 4; ++e) {
        __nv_bfloat16 h = __float2bfloat16_rn(v[e]);
        __nv_bfloat16 l = __float2bfloat16_rn(v[e] - __bfloat162float(h));
        hb[e] = *(uint16_t*)&h;
        lb_[e] = *(uint16_t*)&l;
    }
    uint2 oh, ol;
    oh.x = (uint32_t)hb[0] | ((uint32_t)hb[1] << 16);
    oh.y = (uint32_t)hb[2] | ((uint32_t)hb[3] << 16);
    ol.x = (uint32_t)lb_[0] | ((uint32_t)lb_[1] << 16);
    ol.y = (uint32_t)lb_[2] | ((uint32_t)lb_[3] << 16);
    g_wfh[idx] = oh;
    g_wfl[idx] = ol;
}

// ---------------- input embed: f32x2 tiled GEMM + LN + GELU (+ bf16 split planes) ----------------
__global__ void k_input(const float* __restrict__ feat, const int* __restrict__ opcode,
                        const float* __restrict__ depth, const float* __restrict__ emb,
                        const float* __restrict__ W, const float* __restrict__ b,
                        const float* __restrict__ lg, const float* __restrict__ lb, int N) {
    extern __shared__ float xs[];   // [205][XSTR]
    int tid = threadIdx.x, lane = tid & 31, wp = tid >> 5;
    int n0 = blockIdx.x * 64;
    for (int i = tid; i < 64 * 140; i += 256) {
        int n = i / 140, k = i - n * 140;
        int gn = n0 + n; if (gn >= N) gn = N - 1;
        xs[k * XSTR + n] = feat[(size_t)gn * 140 + k];
    }
    for (int i = tid; i < 64 * 64; i += 256) {
        int n = i >> 6, k = i & 63;
        int gn = n0 + n; if (gn >= N) gn = N - 1;
        int op = opcode[gn]; op = op < 0 ? 0 : (op > 119 ? 119 : op);
        xs[(140 + k) * XSTR + n] = emb[op * 64 + k];
    }
    if (tid < 64) {
        int gn = n0 + tid; if (gn >= N) gn = N - 1;
        xs[204 * XSTR + tid] = depth[gn];
    }
    __syncthreads();

    int ng = wp, c0 = lane * 4;
    u64 acc2[4][4];
    #pragma unroll
    for (int p = 0; p < 4; ++p)
        #pragma unroll
        for (int c = 0; c < 4; ++c) acc2[p][c] = 0ull;
    #pragma unroll 4
    for (int k = 0; k < 205; ++k) {
        float4 w4 = *(const float4*)&W[k * HID + c0];
        u64 wd[4] = {dup2(w4.x), dup2(w4.y), dup2(w4.z), dup2(w4.w)};
        const u64* xp = (const u64*)&xs[k * XSTR + ng * 8];
        u64 xv[4] = {xp[0], xp[1], xp[2], xp[3]};
        #pragma unroll
        for (int p = 0; p < 4; ++p)
            #pragma unroll
            for (int c = 0; c < 4; ++c) fma2(acc2[p][c], xv[p], wd[c]);
    }
    float av[8][4];
    #pragma unroll
    for (int p = 0; p < 4; ++p)
        #pragma unroll
        for (int c = 0; c < 4; ++c) {
            float2 t = unpk(acc2[p][c]);
            av[2 * p][c] = t.x; av[2 * p + 1][c] = t.y;
        }
    float4 b4 = *(const float4*)&b[c0];
    float4 g4 = *(const float4*)&lg[c0];
    float4 e4 = *(const float4*)&lb[c0];
    float mu[8], iv[8];
    #pragma unroll
    for (int j = 0; j < 8; ++j) {
        av[j][0] += b4.x; av[j][1] += b4.y; av[j][2] += b4.z; av[j][3] += b4.w;
        mu[j] = wred(av[j][0] + av[j][1] + av[j][2] + av[j][3]) * (1.f / HID);
    }
    #pragma unroll
    for (int j = 0; j < 8; ++j) {
        float dx = av[j][0] - mu[j], dy = av[j][1] - mu[j];
        float dz = av[j][2] - mu[j], dw = av[j][3] - mu[j];
        iv[j] = rsqrtf(wred(dx * dx + dy * dy + dz * dz + dw * dw) * (1.f / HID) + 1e-5f);
    }
    #pragma unroll
    for (int j = 0; j < 8; ++j) {
        int gn = n0 + ng * 8 + j;
        if (gn < N) {
            float o0 = gelu_f((av[j][0] - mu[j]) * iv[j] * g4.x + e4.x);
            float o1 = gelu_f((av[j][1] - mu[j]) * iv[j] * g4.y + e4.y);
            float o2 = gelu_f((av[j][2] - mu[j]) * iv[j] * g4.z + e4.z);
            float o3 = gelu_f((av[j][3] - mu[j]) * iv[j] * g4.w + e4.w);
            *(float4*)&g_h[(size_t)gn * HID + c0] = make_float4(o0, o1, o2, o3);
            __nv_bfloat162 h0, h1, l0, l1;
            h0.x = __float2bfloat16_rn(o0); h0.y = __float2bfloat16_rn(o1);
            h1.x = __float2bfloat16_rn(o2); h1.y = __float2bfloat16_rn(o3);
            l0.x = __float2bfloat16_rn(o0 - __bfloat162float(h0.x));
            l0.y = __float2bfloat16_rn(o1 - __bfloat162float(h0.y));
            l1.x = __float2bfloat16_rn(o2 - __bfloat162float(h1.x));
            l1.y = __float2bfloat16_rn(o3 - __bfloat162float(h1.y));
            *(__nv_bfloat162*)&g_hh[(size_t)gn * HID + c0] = h0;
            *(__nv_bfloat162*)&g_hh[(size_t)gn * HID + c0 + 2] = h1;
            *(__nv_bfloat162*)&g_hl[(size_t)gn * HID + c0] = l0;
            *(__nv_bfloat162*)&g_hl[(size_t)gn * HID + c0 + 2] = l1;
        }
    }
}

// ---------------- mean aggregation: warp per node, writes bf16 hi/lo planes ----------------
__global__ void k_agg(int N) {
    int gw = (blockIdx.x * blockDim.x + threadIdx.x) >> 5;
    int lane = threadIdx.x & 31;
    if (gw >= N) return;
    int rs = g_rowstart[gw], re = g_rowstart[gw + 1];
    float4 acc = make_float4(0.f, 0.f, 0.f, 0.f);
    for (int e = rs; e < re; ++e) {
        int s = g_csr[e];
        float4 v = *(const float4*)&g_h[(size_t)s * HID + lane * 4];
        acc.x += v.x; acc.y += v.y; acc.z += v.z; acc.w += v.w;
    }
    float idg = g_invdeg[gw];
    acc.x *= idg; acc.y *= idg; acc.z *= idg; acc.w *= idg;
    __nv_bfloat162 h0, h1, l0, l1;
    h0.x = __float2bfloat16_rn(acc.x); h0.y = __float2bfloat16_rn(acc.y);
    h1.x = __float2bfloat16_rn(acc.z); h1.y = __float2bfloat16_rn(acc.w);
    l0.x = __float2bfloat16_rn(acc.x - __bfloat162float(h0.x));
    l0.y = __float2bfloat16_rn(acc.y - __bfloat162float(h0.y));
    l1.x = __float2bfloat16_rn(acc.z - __bfloat162float(h1.x));
    l1.y = __float2bfloat16_rn(acc.w - __bfloat162float(h1.y));
    size_t off = (size_t)gw * HID + lane * 4;
    *(__nv_bfloat162*)&g_aggh[off] = h0;
    *(__nv_bfloat162*)&g_aggh[off + 2] = h1;
    *(__nv_bfloat162*)&g_aggl[off] = l0;
    *(__nv_bfloat162*)&g_aggl[off + 2] = l1;
}

// ---------------- SAGE layer: bf16 3-mma split; B fragments via direct LDG ----------------
// smem: sAh[64][264], sAl[64][264] (bf16), pS/pQ LN partials. 69 KB -> 3 blocks/SM.
__global__ void __launch_bounds__(256) k_layer(
        const float* __restrict__ bl, const float* __restrict__ lg,
        const float* __restrict__ lb, int layer, int N) {
    extern __shared__ char smb[];
    __nv_bfloat16* sAh = (__nv_bfloat16*)smb;                 // 33792 B
    __nv_bfloat16* sAl = (__nv_bfloat16*)(smb + 33792);       // 33792 B
    float* pS = (float*)(smb + 67584);                        // 128 f
    float* pQ = (float*)(smb + 68096);                        // 128 f
    int tid = threadIdx.x, lane = tid & 31, w = tid >> 5;
    int n0 = blockIdx.x * 64;

    // stage A: 4096 16B-chunks (2 planes x 64 rows x 32 chunks)
    #pragma unroll
    for (int it = 0; it < 16; ++it) {
        int c = it * 256 + tid;
        int plane = c >> 11, rc = c & 2047;
        int row = rc >> 5, chk = rc & 31;
        int gn = n0 + row; if (gn >= N) gn = N - 1;
        const __nv_bfloat16* src;
        if (chk < 16) src = (plane ? g_aggl : g_aggh) + (size_t)gn * HID + chk * 8;
        else          src = (plane ? g_hl : g_hh) + (size_t)gn * HID + (chk - 16) * 8;
        uint4 v = *(const uint4*)src;
        __nv_bfloat16* dst = (plane ? sAl : sAh) + row * ASTR + chk * 8;
        *(uint4*)dst = v;
    }
    __syncthreads();

    int mt = w >> 1, nh = w & 1;
    float d[8][4];
    #pragma unroll
    for (int j = 0; j < 8; ++j)
        #pragma unroll
        for (int e = 0; e < 4; ++e) d[j][e] = 0.f;

    int arow = mt * 16 + (lane & 7) + ((lane >> 3) & 1) * 8;
    uint32_t aAh = s2u(sAh) + (arow * ASTR + (lane >> 4) * 8) * 2;
    uint32_t aAl = aAh + 33792;
    const uint2* wfh = g_wfh + (layer << 13);
    const uint2* wfl = g_wfl + (layer << 13);

    for (int kt = 0; kt < 16; ++kt) {
        uint32_t ah0, ah1, ah2, ah3, al0, al1, al2, al3;
        asm volatile("ldmatrix.sync.aligned.m8n8.x4.shared.b16 {%0,%1,%2,%3}, [%4];"
                     : "=r"(ah0), "=r"(ah1), "=r"(ah2), "=r"(ah3) : "r"(aAh + kt * 32));
        asm volatile("ldmatrix.sync.aligned.m8n8.x4.shared.b16 {%0,%1,%2,%3}, [%4];"
                     : "=r"(al0), "=r"(al1), "=r"(al2), "=r"(al3) : "r"(aAl + kt * 32));
        #pragma unroll
        for (int j = 0; j < 8; ++j) {
            int nt = nh * 8 + j;
            uint2 bh = wfh[(kt << 9) | (nt << 5) | lane];
            uint2 bL = wfl[(kt << 9) | (nt << 5) | lane];
            asm volatile("mma.sync.aligned.m16n8k16.row.col.f32.bf16.bf16.f32 "
                         "{%0,%1,%2,%3}, {%4,%5,%6,%7}, {%8,%9}, {%0,%1,%2,%3};"
                         : "+f"(d[j][0]), "+f"(d[j][1]), "+f"(d[j][2]), "+f"(d[j][3])
                         : "r"(ah0), "r"(ah1), "r"(ah2), "r"(ah3), "r"(bh.x), "r"(bh.y));
            asm volatile("mma.sync.aligned.m16n8k16.row.col.f32.bf16.bf16.f32 "
                         "{%0,%1,%2,%3}, {%4,%5,%6,%7}, {%8,%9}, {%0,%1,%2,%3};"
                         : "+f"(d[j][0]), "+f"(d[j][1]), "+f"(d[j][2]), "+f"(d[j][3])
                         : "r"(al0), "r"(al1), "r"(al2), "r"(al3), "r"(bh.x), "r"(bh.y));
            asm volatile("mma.sync.aligned.m16n8k16.row.col.f32.bf16.bf16.f32 "
                         "{%0,%1,%2,%3}, {%4,%5,%6,%7}, {%8,%9}, {%0,%1,%2,%3};"
                         : "+f"(d[j][0]), "+f"(d[j][1]), "+f"(d[j][2]), "+f"(d[j][3])
                         : "r"(ah0), "r"(ah1), "r"(ah2), "r"(ah3), "r"(bL.x), "r"(bL.y));
        }
    }

    int g = lane >> 2, q = lane & 3;
    int lr0 = mt * 16 + g, lr1 = lr0 + 8;
    int gn0 = n0 + lr0, gn1 = n0 + lr1;
    int cg0 = gn0 < N ? gn0 : N - 1, cg1 = gn1 < N ? gn1 : N - 1;
    float s0 = 0.f, s1 = 0.f, q0 = 0.f, q1 = 0.f;
    #pragma unroll
    for (int j = 0; j < 8; ++j) {
        int cp = nh * 64 + j * 8 + 2 * q;
        float2 bb = *(const float2*)&bl[cp];
        float2 h0 = *(const float2*)&g_h[(size_t)cg0 * HID + cp];
        float2 h1 = *(const float2*)&g_h[(size_t)cg1 * HID + cp];
        float y00 = h0.x + gelu_f(d[j][0] + bb.x);
        float y01 = h0.y + gelu_f(d[j][1] + bb.y);
        float y10 = h1.x + gelu_f(d[j][2] + bb.x);
        float y11 = h1.y + gelu_f(d[j][3] + bb.y);
        d[j][0] = y00; d[j][1] = y01; d[j][2] = y10; d[j][3] = y11;
        s0 += y00 + y01; s1 += y10 + y11;
        q0 += y00 * y00 + y01 * y01; q1 += y10 * y10 + y11 * y11;
    }
    #pragma unroll
    for (int o = 1; o <= 2; o <<= 1) {
        s0 += __shfl_xor_sync(0xffffffffu, s0, o);
        s1 += __shfl_xor_sync(0xffffffffu, s1, o);
        q0 += __shfl_xor_sync(0xffffffffu, q0, o);
        q1 += __shfl_xor_sync(0xffffffffu, q1, o);
    }
    if (q == 0) {
        pS[lr0 * 2 + nh] = s0; pS[lr1 * 2 + nh] = s1;
        pQ[lr0 * 2 + nh] = q0; pQ[lr1 * 2 + nh] = q1;
    }
    __syncthreads();
    float mu0 = (pS[lr0 * 2] + pS[lr0 * 2 + 1]) * (1.f / HID);
    float mu1 = (pS[lr1 * 2] + pS[lr1 * 2 + 1]) * (1.f / HID);
    float v0 = (pQ[lr0 * 2] + pQ[lr0 * 2 + 1]) * (1.f / HID) - mu0 * mu0;
    float v1 = (pQ[lr1 * 2] + pQ[lr1 * 2 + 1]) * (1.f / HID) - mu1 * mu1;
    float iv0 = rsqrtf(v0 + 1e-5f), iv1 = rsqrtf(v1 + 1e-5f);
    #pragma unroll
    for (int j = 0; j < 8; ++j) {
        int cp = nh * 64 + j * 8 + 2 * q;
        float2 lgp = *(const float2*)&lg[cp];
        float2 lbp = *(const float2*)&lb[cp];
        if (gn0 < N) {
            float ox = (d[j][0] - mu0) * iv0 * lgp.x + lbp.x;
            float oy = (d[j][1] - mu0) * iv0 * lgp.y + lbp.y;
            *(float2*)&g_h[(size_t)gn0 * HID + cp] = make_float2(ox, oy);
            __nv_bfloat162 hh, ll;
            hh.x = __float2bfloat16_rn(ox); hh.y = __float2bfloat16_rn(oy);
            ll.x = __float2bfloat16_rn(ox - __bfloat162float(hh.x));
            ll.y = __float2bfloat16_rn(oy - __bfloat162float(hh.y));
            *(__nv_bfloat162*)&g_hh[(size_t)gn0 * HID + cp] = hh;
            *(__nv_bfloat162*)&g_hl[(size_t)gn0 * HID + cp] = ll;
        }
        if (gn1 < N) {
            float ox = (d[j][2] - mu1) * iv1 * lgp.x + lbp.x;
            float oy = (d[j][3] - mu1) * iv1 * lgp.y + lbp.y;
            *(float2*)&g_h[(size_t)gn1 * HID + cp] = make_float2(ox, oy);
            __nv_bfloat162 hh, ll;
            hh.x = __float2bfloat16_rn(ox); hh.y = __float2bfloat16_rn(oy);
            ll.x = __float2bfloat16_rn(ox - __bfloat162float(hh.x));
            ll.y = __float2bfloat16_rn(oy - __bfloat162float(hh.y));
            *(__nv_bfloat162*)&g_hh[(size_t)gn1 * HID + cp] = hh;
            *(__nv_bfloat162*)&g_hl[(size_t)gn1 * HID + cp] = ll;
        }
    }
}

// ---------------- global mean of h (deterministic 2-stage) ----------------
__global__ void k_gmean1(int N) {
    int col = threadIdx.x, blk = blockIdx.x;
    int per = (N + 511) / 512;
    int a = blk * per, b = a + per; if (b > N) b = N;
    float acc = 0.f;
    for (int n = a; n < b; ++n) acc += g_h[(size_t)n * HID + col];
    g_partial[blk * HID + col] = acc;
}
__global__ void k_gmean2(int N) {
    int col = threadIdx.x;
    float acc = 0.f;
    for (int b = 0; b < 512; ++b) acc += g_partial[b * HID + col];
    g_ge[col] = acc / (float)N;
}

// ---------------- base[nc] = h[cfg_id[nc]] @ cfg_w[:128] + cfg_b ----------------
__global__ void k_base(const int* __restrict__ ids, const float* __restrict__ W,
                       const float* __restrict__ b, int NC) {
    __shared__ float row[HID];
    int nc = blockIdx.x, col = threadIdx.x;
    int nd = ids[nc];
    row[col] = g_h[(size_t)nd * HID + col];
    __syncthreads();
    float acc = b[col];
    for (int k = 0; k < HID; ++k) acc += row[k] * W[k * HID + col];
    g_base[nc * HID + col] = acc;
}

// ---------------- scoring: proj + SE + chunk softmax (f32x2 col-pairs, R9 structure) ----------------
__global__ void k_score(const float* __restrict__ cfgf, const float* __restrict__ cfg_w,
                        const float* __restrict__ w1, const float* __restrict__ b1,
                        const float* __restrict__ w2s, const float* __restrict__ b2,
                        const float* __restrict__ temp, int C, int NC) {
    extern __shared__ unsigned char smx[];
    __half* projs = (__half*)smx;                      // 512*128
    float* base_s = (float*)(smx + CH * HID * 2);      // 128
    float* w18 = base_s + HID;                         // 18*128
    float* sw1 = w18 + 18 * HID;                       // 128*16
    float* sw2 = sw1 + HID * 16;                       // 16*128
    float* sb1 = sw2 + 16 * HID;                       // 16
    float* sb2 = sb1 + 16;                             // 128
    int tid = threadIdx.x;
    int chunk = blockIdx.x, nc = blockIdx.y;
    for (int i = tid; i < 18 * HID; i += CH) w18[i] = cfg_w[128 * HID + i];
    for (int i = tid; i < HID * 16; i += CH) sw1[i] = w1[i];
    for (int i = tid; i < 16 * HID; i += CH) sw2[i] = w2s[i];
    if (tid < 16) sb1[tid] = b1[tid];
    if (tid < HID) sb2[tid] = b2[tid];
    if (tid < HID) base_s[tid] = g_base[nc * HID + tid];
    __syncthreads();
    int c = tid;
    int cg = chunk * CH + c;
    u64 fd[18];
    #pragma unroll
    for (int j = 0; j < 18; ++j) fd[j] = dup2(cfgf[((size_t)cg * NC + nc) * 18 + j]);
    u64 s12[8];
    #pragma unroll
    for (int r = 0; r < 8; ++r) s12[r] = *(const u64*)&sb1[r * 2];
    for (int col = 0; col < HID; col += 2) {
        u64 v2 = *(const u64*)&base_s[col];
        #pragma unroll
        for (int j = 0; j < 18; ++j) fma2(v2, fd[j], *(const u64*)&w18[j * HID + col]);
        float2 vv = unpk(v2);
        float va = gelu_f(vv.x), vb = gelu_f(vv.y);
        projs[col * CH + c] = __float2half(va);
        projs[(col + 1) * CH + c] = __float2half(vb);
        u64 vda = dup2(va), vdb = dup2(vb);
        #pragma unroll
        for (int r = 0; r < 8; ++r) {
            fma2(s12[r], vda, *(const u64*)&sw1[col * 16 + r * 2]);
            fma2(s12[r], vdb, *(const u64*)&sw1[(col + 1) * 16 + r * 2]);
        }
    }
    u64 s1d[16];
    #pragma unroll
    for (int r = 0; r < 8; ++r) {
        float2 t = unpk(s12[r]);
        s1d[2 * r] = dup2(fmaxf(t.x, 0.f));
        s1d[2 * r + 1] = dup2(fmaxf(t.y, 0.f));
    }
    for (int col = 0; col < HID; col += 2) {
        u64 z2 = *(const u64*)&sb2[col];
        #pragma unroll
        for (int r = 0; r < 16; ++r) fma2(z2, s1d[r], *(const u64*)&sw2[r * HID + col]);
        float2 zz = unpk(z2);
        float sa = 1.f / (1.f + __expf(-zz.x));
        float sb_ = 1.f / (1.f + __expf(-zz.y));
        projs[col * CH + c] = __float2half(__half2float(projs[col * CH + c]) * sa);
        projs[(col + 1) * CH + c] = __float2half(__half2float(projs[(col + 1) * CH + c]) * sb_);
    }
    __syncthreads();
    float invT = 1.f / temp[0];
    int lane = tid & 31, wid = tid >> 5;
    for (int ci = 0; ci < 8; ++ci) {
        int col = wid + ci * 16;
        float v[16], m = -1e30f;
        #pragma unroll
        for (int i = 0; i < 16; ++i) {
            v[i] = __half2float(projs[col * CH + lane + i * 32]);
            m = fmaxf(m, v[i]);
        }
        #pragma unroll
        for (int o = 16; o; o >>= 1) m = fmaxf(m, __shfl_xor_sync(0xffffffffu, m, o));
        float ex[16];
        float se = 0.f;
        #pragma unroll
        for (int i = 0; i < 16; ++i) { ex[i] = __expf((v[i] - m) * invT); se += ex[i]; }
        se = wred(se);
        float inv_se = 1.f / se;
        #pragma unroll
        for (int i = 0; i < 16; ++i)
            projs[col * CH + lane + i * 32] = __float2half(v[i] * ex[i] * inv_se);
    }
    __syncthreads();
    for (int i = tid; i < CH * HID; i += CH) {
        int cl = i >> 7, col = i & 127;
        g_slab[((size_t)(chunk * CH + cl) * NC + nc) * HID + col] = projs[col * CH + cl];
    }
}

// ---------------- slab reduce ----------------
__global__ void k_reduce(int C, int NC) {
    __shared__ float red[8][HID];
    int c = blockIdx.x, tid = threadIdx.x;
    int cg = (tid & 15) * 8, rg = tid >> 4;
    float a[8];
    #pragma unroll
    for (int i = 0; i < 8; ++i) a[i] = 0.f;
    for (int nc = rg; nc < NC; nc += 8) {
        uint4 v = *(const uint4*)&g_slab[((size_t)c * NC + nc) * HID + cg];
        const __half2* h2 = (const __half2*)&v;
        #pragma unroll
        for (int i = 0; i < 4; ++i) {
            float2 f = __half22float2(h2[i]);
            a[2 * i] += f.x; a[2 * i + 1] += f.y;
        }
    }
    #pragma unroll
    for (int i = 0; i < 8; ++i) red[rg][cg + i] = a[i];
    __syncthreads();
    if (tid < HID) {
        float s = 0.f;
        #pragma unroll
        for (int r = 0; r < 8; ++r) s += red[r][tid];
        g_ce[c * HID + tid] = s / (float)NC;
    }
}

// ---------------- head MLP ----------------
__global__ void k_head(const float* __restrict__ w1, const float* __restrict__ b1,
                       const float* __restrict__ w2, const float* __restrict__ b2,
                       const float* __restrict__ w3, const float* __restrict__ b3,
                       float* __restrict__ out, int N, int C) {
    __shared__ float ges[HID], ces[HID], x1[HID], x2[64];
    int c = blockIdx.x, col = threadIdx.x;
    ges[col] = g_ge[col];
    ces[col] = g_ce[c * HID + col];
    __syncthreads();
    float acc = b1[col];
    for (int k = 0; k < HID; ++k) acc += ges[k] * w1[k * HID + col];
    for (int k = 0; k < HID; ++k) acc += ces[k] * w1[(HID + k) * HID + col];
    x1[col] = gelu_f(acc);
    __syncthreads();
    if (col < 64) {
        float a2 = b2[col];
        for (int k = 0; k < HID; ++k) a2 += x1[k] * w2[k * 64 + col];
        x2[col] = gelu_f(a2);
    }
    __syncthreads();
    if (col == 0) {
        float s = b3[0];
        for (int k = 0; k < 64; ++k) s += x2[k] * w3[k];
        out[c] = s;
    }
}

extern "C" void kernel_launch(void* const* d_in, const int* in_sizes, int n_in,
                              void* d_out, int out_size) {
    const float* node_feat = (const float*)d_in[0];
    const int*   node_opc  = (const int*)d_in[1];
    const float* topo      = (const float*)d_in[2];
    const int*   ei        = (const int*)d_in[3];
    const int*   cfg_ids   = (const int*)d_in[4];
    const float* cfg_feat  = (const float*)d_in[5];
    const float* temp      = (const float*)d_in[6];
    const float* opc_emb   = (const float*)d_in[7];
    const float* in_w      = (const float*)d_in[8];
    const float* in_b      = (const float*)d_in[9];
    const float* in_g      = (const float*)d_in[10];
    const float* in_beta   = (const float*)d_in[11];
    const float* sage_Wl   = (const float*)d_in[12];
    const float* sage_bl   = (const float*)d_in[13];
    const float* sage_Wr   = (const float*)d_in[14];
    const float* ln_g      = (const float*)d_in[15];
    const float* ln_b      = (const float*)d_in[16];
    const float* cfg_w     = (const float*)d_in[17];
    const float* cfg_b     = (const float*)d_in[18];
    const float* se_w1     = (const float*)d_in[19];
    const float* se_b1     = (const float*)d_in[20];
    const float* se_w2     = (const float*)d_in[21];
    const float* se_b2     = (const float*)d_in[22];
    const float* h_w1      = (const float*)d_in[23];
    const float* h_b1      = (const float*)d_in[24];
    const float* h_w2      = (const float*)d_in[25];
    const float* h_b2      = (const float*)d_in[26];
    const float* h_w3      = (const float*)d_in[27];
    const float* h_b3      = (const float*)d_in[28];

    int N  = in_sizes[1];
    int M  = in_sizes[3] / 2;
    int NC = in_sizes[4];
    int C  = in_sizes[5] / (NC * 18);
    int chunks = C / CH;
    int nblk = (N + 63) / 64;

    size_t in_smem = (size_t)205 * XSTR * 4;
    size_t ly_smem = 68608;
    cudaFuncSetAttribute(k_input, cudaFuncAttributeMaxDynamicSharedMemorySize, (int)in_smem);
    cudaFuncSetAttribute(k_layer, cudaFuncAttributeMaxDynamicSharedMemorySize, (int)ly_smem);

    k_zero<<<(N + 255) / 256, 256>>>(N);
    k_deg<<<(M + 255) / 256, 256>>>(ei, M);
    int sb = (N + 1023) / 1024;
    k_scan1<<<sb, 1024>>>(N);
    k_input<<<nblk, 256, in_smem>>>(node_feat, node_opc, topo, opc_emb,
                                    in_w, in_b, in_g, in_beta, N);
    k_wsplit<<<128, 256>>>(sage_Wl, sage_Wr);
    k_scan2<<<1, 32>>>(sb);
    k_scan3<<<(N + 255) / 256, 256>>>(N);
    k_posinv<<<(N + 255) / 256, 256>>>(N);
    k_scatter<<<(M + 255) / 256, 256>>>(ei, M);
    for (int l = 0; l < 4; ++l) {
        k_agg<<<(N + 7) / 8, 256>>>(N);
        k_layer<<<nblk, 256, ly_smem>>>(sage_bl + l * HID,
                                        ln_g + l * HID, ln_b + l * HID, l, N);
    }
    k_gmean1<<<512, 128>>>(N);
    k_gmean2<<<1, 128>>>(N);
    k_base<<<NC, 128>>>(cfg_ids, cfg_w, cfg_b, NC);

    size_t score_smem = (size_t)CH * HID * 2 +
                        (HID + 18 * HID + HID * 16 + 16 * HID + 16 + HID) * sizeof(float);
    cudaFuncSetAttribute(k_score, cudaFuncAttributeMaxDynamicSharedMemorySize, (int)score_smem);
    dim3 sg(chunks, NC);
    k_score<<<sg, CH, score_smem>>>(cfg_feat, cfg_w, se_w1, se_b1, se_w2, se_b2,
                                    temp, C, NC);
    k_reduce<<<C, 128>>>(C, NC);
    k_head<<<C, 128>>>(h_w1, h_b1, h_w2, h_b2, h_w3, h_b3, (float*)d_out, N, C);
}